// round 2
// baseline (speedup 1.0000x reference)
#include <cuda_runtime.h>
#include <cstdint>

// Problem constants
#define MM 1024
#define NN 4096
#define KK 4096
#define HH 32
#define DD 128
#define PP 4096
#define LL (PP + MM)   // 5120

#define BQ 64
#define BKV 64

// Scratch for Q/K/V projections (48 MB total) — __device__ globals per alloc rules.
__device__ float g_Q[MM * NN];
__device__ float g_K[MM * NN];
__device__ float g_V[MM * NN];

// ---------------- packed f32x2 helpers (FFMA2 path, 2x fp32 throughput) ----------------
__device__ __forceinline__ unsigned long long pk2(float lo, float hi) {
    unsigned long long r;
    asm("mov.b64 %0, {%1,%2};" : "=l"(r) : "f"(lo), "f"(hi));
    return r;
}
__device__ __forceinline__ void fma2(unsigned long long& c, unsigned long long a, unsigned long long b) {
    asm("fma.rn.f32x2 %0, %1, %2, %0;" : "+l"(c) : "l"(a), "l"(b));
}
__device__ __forceinline__ void mul2(unsigned long long& c, unsigned long long a) {
    asm("mul.rn.f32x2 %0, %0, %1;" : "+l"(c) : "l"(a));
}
__device__ __forceinline__ float2 upk(unsigned long long v) {
    float2 f;
    asm("mov.b64 {%0,%1}, %2;" : "=f"(f.x), "=f"(f.y) : "l"(v));
    return f;
}

// ---------------- QKV projection: C = X @ W, 128x128x8 tiles ----------------
// grid = (NN/128, MM/128, 3); block = 256
__global__ __launch_bounds__(256, 2)
void qkv_gemm_kernel(const float* __restrict__ X, const float* __restrict__ Wq,
                     const float* __restrict__ Wk, const float* __restrict__ Wv) {
    const float* W = (blockIdx.z == 0) ? Wq : (blockIdx.z == 1) ? Wk : Wv;
    float* C = (blockIdx.z == 0) ? g_Q : (blockIdx.z == 1) ? g_K : g_V;

    __shared__ float As[8][128];   // k-major
    __shared__ float Bs[8][128];   // k-major (natural: W rows are n-contiguous)

    const int tid = threadIdx.x;
    const int tx = tid & 15;        // 16 col-thread groups
    const int ty = tid >> 4;        // 16 row-thread groups
    const int row0 = blockIdx.y * 128;
    const int col0 = blockIdx.x * 128;

    // load mapping
    const int aRow = tid >> 1;             // 0..127
    const int aCol = (tid & 1) * 4;        // 0 or 4
    const int bRow = tid >> 5;             // 0..7
    const int bCol = (tid & 31) * 4;       // 0..124

    const float* Ap = X + (size_t)(row0 + aRow) * KK + aCol;
    const float* Bp = W + (size_t)bRow * NN + col0 + bCol;

    unsigned long long acc[8][4] = {};  // 8 rows x 8 cols as 4 f32x2 pairs
                                        // pairs 0,1 -> cols tx*4..+3 ; pairs 2,3 -> cols 64+tx*4..+3

    float4 av = *(const float4*)Ap;
    float4 bv = *(const float4*)Bp;

    for (int k0 = 0; k0 < KK; k0 += 8) {
        As[aCol + 0][aRow] = av.x;
        As[aCol + 1][aRow] = av.y;
        As[aCol + 2][aRow] = av.z;
        As[aCol + 3][aRow] = av.w;
        *(float4*)&Bs[bRow][bCol] = bv;
        __syncthreads();

        if (k0 + 8 < KK) {  // register prefetch of next tile
            av = *(const float4*)(Ap + k0 + 8);
            bv = *(const float4*)(Bp + (size_t)(k0 + 8) * NN);
        }

#pragma unroll
        for (int kk = 0; kk < 8; kk++) {
            float4 b0 = *(const float4*)&Bs[kk][tx * 4];        // conflict-free
            float4 b1 = *(const float4*)&Bs[kk][64 + tx * 4];   // conflict-free
            unsigned long long bp0 = pk2(b0.x, b0.y);
            unsigned long long bp1 = pk2(b0.z, b0.w);
            unsigned long long bp2 = pk2(b1.x, b1.y);
            unsigned long long bp3 = pk2(b1.z, b1.w);
            float4 a0 = *(const float4*)&As[kk][ty * 8];        // broadcast across tx
            float4 a1 = *(const float4*)&As[kk][ty * 8 + 4];
            float ar[8] = {a0.x, a0.y, a0.z, a0.w, a1.x, a1.y, a1.z, a1.w};
#pragma unroll
            for (int i = 0; i < 8; i++) {
                unsigned long long ap = pk2(ar[i], ar[i]);
                fma2(acc[i][0], ap, bp0);
                fma2(acc[i][1], ap, bp1);
                fma2(acc[i][2], ap, bp2);
                fma2(acc[i][3], ap, bp3);
            }
        }
        __syncthreads();
    }

#pragma unroll
    for (int i = 0; i < 8; i++) {
        float2 c0 = upk(acc[i][0]), c1 = upk(acc[i][1]);
        float2 c2 = upk(acc[i][2]), c3 = upk(acc[i][3]);
        size_t base = (size_t)(row0 + ty * 8 + i) * NN + col0;
        *(float4*)&C[base + tx * 4]      = make_float4(c0.x, c0.y, c1.x, c1.y);
        *(float4*)&C[base + 64 + tx * 4] = make_float4(c2.x, c2.y, c3.x, c3.y);
    }
}

// ---------------- Flash attention, fp32, no 1/sqrt(D) scaling ----------------
// grid = (MM/BQ, HH); block = 256; dynamic smem = 80 KB
// Per thread: rows ty*4..ty*4+3 ; S-cols tx*4..tx*4+3 ; O-cols {tx*4..+3} and {64+tx*4..+3}
__global__ __launch_bounds__(256, 2)
void attn_kernel(const float* __restrict__ cK, const float* __restrict__ cV,
                 float* __restrict__ out) {
    extern __shared__ float sm[];
    float* sQ  = sm;                 // swizzled d-major [128][64]
    float* sKV = sm + 128 * 64;      // K phase: swizzled d-major [128][64]; V phase: row-major [64][128]
    float* sP  = sm + 2 * 128 * 64;  // row-major [64][64]

    const int h = blockIdx.y;
    const int q0 = blockIdx.x * BQ;
    const int tid = threadIdx.x;
    const int tx = tid & 15;
    const int ty = tid >> 4;

    // ---- load Q tile (swizzled d-major: slot = d*64 + (r ^ sw(d)), sw(d)=((d>>2)&15)<<2) ----
#pragma unroll
    for (int it = 0; it < 8; it++) {
        int idx = tid + it * 256;
        int r = idx >> 5;
        int d4 = idx & 31;
        float4 v = *(const float4*)&g_Q[(size_t)(q0 + r) * NN + h * DD + d4 * 4];
        int rs = r ^ ((d4 & 15) << 2);
        sQ[(d4 * 4 + 0) * 64 + rs] = v.x;
        sQ[(d4 * 4 + 1) * 64 + rs] = v.y;
        sQ[(d4 * 4 + 2) * 64 + rs] = v.z;
        sQ[(d4 * 4 + 3) * 64 + rs] = v.w;
    }

    float m_i[4], l_i[4];
    unsigned long long acc[4][4] = {};
#pragma unroll
    for (int i = 0; i < 4; i++) { m_i[i] = -1e30f; l_i[i] = 0.0f; }

    __syncthreads();

    for (int t = 0; t < LL / BKV; t++) {
        const int p0 = t * BKV;

        // ---- load K tile (swizzled d-major) ----
#pragma unroll
        for (int it = 0; it < 8; it++) {
            int idx = tid + it * 256;
            int r = idx >> 5;
            int d4 = idx & 31;
            int p = p0 + r;
            const float* src = (p < PP)
                ? (cK + ((size_t)h * PP + p) * DD + d4 * 4)
                : (g_K + (size_t)(p - PP) * NN + h * DD + d4 * 4);
            float4 v = *(const float4*)src;
            int rs = r ^ ((d4 & 15) << 2);
            sKV[(d4 * 4 + 0) * 64 + rs] = v.x;
            sKV[(d4 * 4 + 1) * 64 + rs] = v.y;
            sKV[(d4 * 4 + 2) * 64 + rs] = v.z;
            sKV[(d4 * 4 + 3) * 64 + rs] = v.w;
        }
        __syncthreads();

        // ---- S = Q K^T (64x64 tile), f32x2 pairs over columns ----
        unsigned long long s2[4][2] = {};
#pragma unroll 8
        for (int kk = 0; kk < DD; kk++) {
            int sw = ((kk >> 2) & 15) << 2;
            float4 qv = *(const float4*)&sQ[kk * 64 + ((ty * 4) ^ sw)];   // broadcast
            float4 kv = *(const float4*)&sKV[kk * 64 + ((tx * 4) ^ sw)];  // conflict-free
            unsigned long long k01 = pk2(kv.x, kv.y);
            unsigned long long k23 = pk2(kv.z, kv.w);
            unsigned long long qp;
            qp = pk2(qv.x, qv.x); fma2(s2[0][0], qp, k01); fma2(s2[0][1], qp, k23);
            qp = pk2(qv.y, qv.y); fma2(s2[1][0], qp, k01); fma2(s2[1][1], qp, k23);
            qp = pk2(qv.z, qv.z); fma2(s2[2][0], qp, k01); fma2(s2[2][1], qp, k23);
            qp = pk2(qv.w, qv.w); fma2(s2[3][0], qp, k01); fma2(s2[3][1], qp, k23);
        }

        // ---- online softmax (row groups of 16 lanes) ----
#pragma unroll
        for (int i = 0; i < 4; i++) {
            float2 a0 = upk(s2[i][0]), a1 = upk(s2[i][1]);
            float mx = fmaxf(fmaxf(a0.x, a0.y), fmaxf(a1.x, a1.y));
            mx = fmaxf(mx, __shfl_xor_sync(0xffffffffu, mx, 1));
            mx = fmaxf(mx, __shfl_xor_sync(0xffffffffu, mx, 2));
            mx = fmaxf(mx, __shfl_xor_sync(0xffffffffu, mx, 4));
            mx = fmaxf(mx, __shfl_xor_sync(0xffffffffu, mx, 8));
            float mnew = fmaxf(m_i[i], mx);
            float scale = __expf(m_i[i] - mnew);
            m_i[i] = mnew;
            float e0 = __expf(a0.x - mnew);
            float e1 = __expf(a0.y - mnew);
            float e2 = __expf(a1.x - mnew);
            float e3 = __expf(a1.y - mnew);
            float ls = e0 + e1 + e2 + e3;
            ls += __shfl_xor_sync(0xffffffffu, ls, 1);
            ls += __shfl_xor_sync(0xffffffffu, ls, 2);
            ls += __shfl_xor_sync(0xffffffffu, ls, 4);
            ls += __shfl_xor_sync(0xffffffffu, ls, 8);
            l_i[i] = l_i[i] * scale + ls;
            unsigned long long sc = pk2(scale, scale);
            mul2(acc[i][0], sc); mul2(acc[i][1], sc);
            mul2(acc[i][2], sc); mul2(acc[i][3], sc);
            *(float4*)&sP[(ty * 4 + i) * 64 + tx * 4] = make_float4(e0, e1, e2, e3);
        }
        __syncthreads();   // sP complete, K reads done -> reuse sKV for V

        // ---- load V tile (row-major) ----
#pragma unroll
        for (int it = 0; it < 8; it++) {
            int idx = tid + it * 256;
            int r = idx >> 5;
            int d4 = idx & 31;
            int p = p0 + r;
            const float* src = (p < PP)
                ? (cV + ((size_t)h * PP + p) * DD + d4 * 4)
                : (g_V + (size_t)(p - PP) * NN + h * DD + d4 * 4);
            *(float4*)&sKV[r * DD + d4 * 4] = *(const float4*)src;
        }
        __syncthreads();

        // ---- O += P @ V ----
#pragma unroll 4
        for (int j = 0; j < BKV; j++) {
            float4 v0 = *(const float4*)&sKV[j * DD + tx * 4];        // conflict-free
            float4 v1 = *(const float4*)&sKV[j * DD + 64 + tx * 4];   // conflict-free
            unsigned long long vp0 = pk2(v0.x, v0.y);
            unsigned long long vp1 = pk2(v0.z, v0.w);
            unsigned long long vp2 = pk2(v1.x, v1.y);
            unsigned long long vp3 = pk2(v1.z, v1.w);
#pragma unroll
            for (int i = 0; i < 4; i++) {
                float p = sP[(ty * 4 + i) * 64 + j];   // broadcast
                unsigned long long pp = pk2(p, p);
                fma2(acc[i][0], pp, vp0);
                fma2(acc[i][1], pp, vp1);
                fma2(acc[i][2], pp, vp2);
                fma2(acc[i][3], pp, vp3);
            }
        }
        __syncthreads();   // done with sKV/sP before next tile
    }

    // ---- epilogue: normalize and store ----
#pragma unroll
    for (int i = 0; i < 4; i++) {
        float inv = 1.0f / l_i[i];
        float2 c0 = upk(acc[i][0]), c1 = upk(acc[i][1]);
        float2 c2 = upk(acc[i][2]), c3 = upk(acc[i][3]);
        size_t base = (size_t)(q0 + ty * 4 + i) * NN + h * DD;
        *(float4*)&out[base + tx * 4] =
            make_float4(c0.x * inv, c0.y * inv, c1.x * inv, c1.y * inv);
        *(float4*)&out[base + 64 + tx * 4] =
            make_float4(c2.x * inv, c2.y * inv, c3.x * inv, c3.y * inv);
    }
}

// ---------------- launch ----------------
extern "C" void kernel_launch(void* const* d_in, const int* in_sizes, int n_in,
                              void* d_out, int out_size) {
    const float* X  = (const float*)d_in[0];
    const float* Wq = (const float*)d_in[1];
    const float* Wk = (const float*)d_in[2];
    const float* Wv = (const float*)d_in[3];
    const float* cK = (const float*)d_in[4];
    const float* cV = (const float*)d_in[5];
    float* out = (float*)d_out;

    dim3 g1(NN / 128, MM / 128, 3);
    qkv_gemm_kernel<<<g1, 256>>>(X, Wq, Wk, Wv);

    const int smem_bytes = (128 * 64 + 64 * 128 + 64 * 64) * (int)sizeof(float);  // 80 KB
    cudaFuncSetAttribute(attn_kernel, cudaFuncAttributeMaxDynamicSharedMemorySize, smem_bytes);
    dim3 g2(MM / BQ, HH);
    attn_kernel<<<g2, 256, smem_bytes>>>(cK, cV, out);
}

// round 4
// speedup vs baseline: 1.3142x; 1.3142x over previous
#include <cuda_runtime.h>
#include <cuda_bf16.h>
#include <cstdint>

// Problem constants
#define MM 1024
#define NN 4096
#define KK 4096
#define HH 32
#define DD 128
#define PP 4096
#define LL (PP + MM)   // 5120

#define BQ 64
#define BKV 64

// ---------------- scratch (__device__ globals per alloc rules) ----------------
__device__ float g_Q[MM * NN];
__device__ float g_K[MM * NN];
__device__ float g_V[MM * NN];
// split-bf16 operands
__device__ __nv_bfloat16 g_Xhi[MM * KK];
__device__ __nv_bfloat16 g_Xlo[MM * KK];
__device__ __nv_bfloat16 g_Wthi[3ull * NN * KK];   // W transposed: [z][n][k]
__device__ __nv_bfloat16 g_Wtlo[3ull * NN * KK];

// ================= helpers =================
__device__ __forceinline__ uint32_t smem_to_u32(const void* p) {
    uint32_t a;
    asm("{ .reg .u64 t; cvta.to.shared.u64 t, %1; cvt.u32.u64 %0, t; }" : "=r"(a) : "l"(p));
    return a;
}

__device__ __forceinline__ void cp_async16(uint32_t saddr, const void* gaddr) {
    asm volatile("cp.async.cg.shared.global [%0], [%1], 16;" :: "r"(saddr), "l"(gaddr) : "memory");
}
#define CP_COMMIT() asm volatile("cp.async.commit_group;" ::: "memory")
#define CP_WAIT(n)  asm volatile("cp.async.wait_group %0;" :: "n"(n) : "memory")

__device__ __forceinline__ void ldsm_x4(uint32_t* r, uint32_t addr) {
    asm volatile("ldmatrix.sync.aligned.m8n8.x4.shared.b16 {%0,%1,%2,%3}, [%4];"
                 : "=r"(r[0]), "=r"(r[1]), "=r"(r[2]), "=r"(r[3]) : "r"(addr));
}
__device__ __forceinline__ void ldsm_x2(uint32_t* r, uint32_t addr) {
    asm volatile("ldmatrix.sync.aligned.m8n8.x2.shared.b16 {%0,%1}, [%2];"
                 : "=r"(r[0]), "=r"(r[1]) : "r"(addr));
}

__device__ __forceinline__ void mma16816(float* d, const uint32_t* a, const uint32_t* b) {
    asm volatile(
        "mma.sync.aligned.m16n8k16.row.col.f32.bf16.bf16.f32 "
        "{%0,%1,%2,%3}, {%4,%5,%6,%7}, {%8,%9}, {%0,%1,%2,%3};"
        : "+f"(d[0]), "+f"(d[1]), "+f"(d[2]), "+f"(d[3])
        : "r"(a[0]), "r"(a[1]), "r"(a[2]), "r"(a[3]), "r"(b[0]), "r"(b[1]));
}

// ---------------- packed f32x2 helpers (attention) ----------------
__device__ __forceinline__ unsigned long long pk2(float lo, float hi) {
    unsigned long long r;
    asm("mov.b64 %0, {%1,%2};" : "=l"(r) : "f"(lo), "f"(hi));
    return r;
}
__device__ __forceinline__ void fma2(unsigned long long& c, unsigned long long a, unsigned long long b) {
    asm("fma.rn.f32x2 %0, %1, %2, %0;" : "+l"(c) : "l"(a), "l"(b));
}
__device__ __forceinline__ void mul2(unsigned long long& c, unsigned long long a) {
    asm("mul.rn.f32x2 %0, %0, %1;" : "+l"(c) : "l"(a));
}
__device__ __forceinline__ float2 upk(unsigned long long v) {
    float2 f;
    asm("mov.b64 {%0,%1}, %2;" : "=f"(f.x), "=f"(f.y) : "l"(v));
    return f;
}

// ================= conversion kernels =================
__global__ __launch_bounds__(256)
void convert_x_kernel(const float* __restrict__ X) {
    int i = (blockIdx.x * 256 + threadIdx.x) * 4;
    float4 v = *(const float4*)(X + i);
    float f[4] = {v.x, v.y, v.z, v.w};
    __align__(8) __nv_bfloat16 hi[4];
    __align__(8) __nv_bfloat16 lo[4];
#pragma unroll
    for (int j = 0; j < 4; j++) {
        hi[j] = __float2bfloat16(f[j]);
        lo[j] = __float2bfloat16(f[j] - __bfloat162float(hi[j]));
    }
    *(uint2*)&g_Xhi[i] = *(uint2*)hi;
    *(uint2*)&g_Xlo[i] = *(uint2*)lo;
}

// W [K][N] -> Wt hi/lo [N][K]
__global__ __launch_bounds__(256)
void convert_w_kernel(const float* __restrict__ Wq, const float* __restrict__ Wk,
                      const float* __restrict__ Wv) {
    const int z = blockIdx.z;
    const float* W = (z == 0) ? Wq : (z == 1) ? Wk : Wv;
    __shared__ float t[32][33];
    const int n0 = blockIdx.x * 32;
    const int k0 = blockIdx.y * 32;
    const int tx = threadIdx.x;
    const int ty = threadIdx.y;
#pragma unroll
    for (int i = 0; i < 4; i++)
        t[ty + i * 8][tx] = W[(size_t)(k0 + ty + i * 8) * NN + n0 + tx];
    __syncthreads();
    size_t base = (size_t)z * NN * KK;
#pragma unroll
    for (int i = 0; i < 4; i++) {
        int r = ty + i * 8;
        float v = t[tx][r];
        __nv_bfloat16 h = __float2bfloat16(v);
        __nv_bfloat16 l = __float2bfloat16(v - __bfloat162float(h));
        size_t o = base + (size_t)(n0 + r) * KK + k0 + tx;
        g_Wthi[o] = h;
        g_Wtlo[o] = l;
    }
}

// ================= split-bf16 mma.sync GEMM: C = X @ W =================
// grid = (NN/128, MM/128, 3); block = 256 (8 warps: 2 warp-rows x 4 warp-cols)
#define GBM 128
#define GBN 128
#define GBK 32
#define NCHUNK (KK / GBK)

// smem stage layout: Ahi(8K) Alo(8K) Bhi(8K) Blo(8K) = 32KB; 2 stages = 64KB
#define ST_AHI 0
#define ST_ALO 8192
#define ST_BHI 16384
#define ST_BLO 24576
#define STAGE_SZ 32768
#define GEMM_SMEM (2 * STAGE_SZ)

// swizzled offset inside a [rows][32 bf16] tile (64B rows)
__device__ __forceinline__ uint32_t sw_off(int row, int seg) {
    return (uint32_t)(row * 64 + ((seg ^ (row & 3)) << 4));
}

__global__ __launch_bounds__(256)
void qkv_gemm_mma() {
    extern __shared__ char smem[];
    const uint32_t sb = smem_to_u32(smem);
    const int tid = threadIdx.x;
    const int wid = tid >> 5;
    const int lane = tid & 31;
    const int wm = wid >> 2;          // 0..1  -> rows wm*64
    const int wn = wid & 3;           // 0..3  -> cols wn*32
    const int z = blockIdx.z;
    const int row0 = blockIdx.y * GBM;
    const int col0 = blockIdx.x * GBN;

    const __nv_bfloat16* Ahi = g_Xhi + (size_t)row0 * KK;
    const __nv_bfloat16* Alo = g_Xlo + (size_t)row0 * KK;
    const __nv_bfloat16* Bhi = g_Wthi + (size_t)z * NN * KK + (size_t)col0 * KK;
    const __nv_bfloat16* Blo = g_Wtlo + (size_t)z * NN * KK + (size_t)col0 * KK;

    // loader mapping: 512 16B-chunks per tile; idx = tid + it*256 -> r=idx>>2, s=idx&3
    const int lr0 = tid >> 2, ls0 = (tid & 3);
    const int lr1 = (tid + 256) >> 2, ls1 = ls0;

    auto load_stage = [&](int s, int k0) {
        uint32_t stb = sb + s * STAGE_SZ;
        const size_t go0 = (size_t)lr0 * KK + k0 + ls0 * 8;
        const size_t go1 = (size_t)lr1 * KK + k0 + ls1 * 8;
        uint32_t so0 = sw_off(lr0, ls0), so1 = sw_off(lr1, ls1);
        cp_async16(stb + ST_AHI + so0, Ahi + go0);
        cp_async16(stb + ST_AHI + so1, Ahi + go1);
        cp_async16(stb + ST_ALO + so0, Alo + go0);
        cp_async16(stb + ST_ALO + so1, Alo + go1);
        cp_async16(stb + ST_BHI + so0, Bhi + go0);
        cp_async16(stb + ST_BHI + so1, Bhi + go1);
        cp_async16(stb + ST_BLO + so0, Blo + go0);
        cp_async16(stb + ST_BLO + so1, Blo + go1);
    };

    float acc[4][4][4] = {};  // [mfrag][nfrag][4]

    load_stage(0, 0);
    CP_COMMIT();

    for (int c = 0; c < NCHUNK; ++c) {
        const int s = c & 1;
        if (c + 1 < NCHUNK) {
            load_stage((c + 1) & 1, (c + 1) * GBK);
            CP_COMMIT();
            CP_WAIT(1);
        } else {
            CP_WAIT(0);
        }
        __syncthreads();

        const uint32_t stb = sb + s * STAGE_SZ;
        // per-lane ldmatrix address components
        const int a_row = (lane & 15);          // within 16-row frag
        const int a_seg = (lane >> 4);          // 0/1 -> k segment
        const int b_row = (lane & 7);
        const int b_seg = ((lane >> 3) & 1);

#pragma unroll
        for (int ks = 0; ks < 2; ++ks) {
            const int segb = ks * 2;
            uint32_t ahi[4][4], alo[4][4], bhi[4][2], blo[4][2];
#pragma unroll
            for (int mf = 0; mf < 4; ++mf) {
                uint32_t off = sw_off(wm * 64 + mf * 16 + a_row, segb + a_seg);
                ldsm_x4(ahi[mf], stb + ST_AHI + off);
                ldsm_x4(alo[mf], stb + ST_ALO + off);
            }
#pragma unroll
            for (int nf = 0; nf < 4; ++nf) {
                uint32_t off = sw_off(wn * 32 + nf * 8 + b_row, segb + b_seg);
                ldsm_x2(bhi[nf], stb + ST_BHI + off);
                ldsm_x2(blo[nf], stb + ST_BLO + off);
            }
#pragma unroll
            for (int mf = 0; mf < 4; ++mf)
#pragma unroll
                for (int nf = 0; nf < 4; ++nf) {
                    mma16816(acc[mf][nf], ahi[mf], bhi[nf]);
                    mma16816(acc[mf][nf], ahi[mf], blo[nf]);
                    mma16816(acc[mf][nf], alo[mf], bhi[nf]);
                }
        }
        __syncthreads();
    }

    // epilogue
    float* C = (z == 0) ? g_Q : (z == 1) ? g_K : g_V;
    const int erow = lane >> 2;
    const int ecol = (lane & 3) * 2;
#pragma unroll
    for (int mf = 0; mf < 4; ++mf) {
#pragma unroll
        for (int nf = 0; nf < 4; ++nf) {
            int r = row0 + wm * 64 + mf * 16 + erow;
            int cc = col0 + wn * 32 + nf * 8 + ecol;
            *(float2*)&C[(size_t)r * NN + cc] = make_float2(acc[mf][nf][0], acc[mf][nf][1]);
            *(float2*)&C[(size_t)(r + 8) * NN + cc] = make_float2(acc[mf][nf][2], acc[mf][nf][3]);
        }
    }
}

// ================= Flash attention, fp32 (validated R2 kernel) =================
__global__ __launch_bounds__(256, 2)
void attn_kernel(const float* __restrict__ cK, const float* __restrict__ cV,
                 float* __restrict__ out) {
    extern __shared__ float sm[];
    float* sQ  = sm;                 // swizzled d-major [128][64]
    float* sKV = sm + 128 * 64;      // K phase: swizzled d-major; V phase: row-major [64][128]
    float* sP  = sm + 2 * 128 * 64;  // row-major [64][64]

    const int h = blockIdx.y;
    const int q0 = blockIdx.x * BQ;
    const int tid = threadIdx.x;
    const int tx = tid & 15;
    const int ty = tid >> 4;

#pragma unroll
    for (int it = 0; it < 8; it++) {
        int idx = tid + it * 256;
        int r = idx >> 5;
        int d4 = idx & 31;
        float4 v = *(const float4*)&g_Q[(size_t)(q0 + r) * NN + h * DD + d4 * 4];
        int rs = r ^ ((d4 & 15) << 2);
        sQ[(d4 * 4 + 0) * 64 + rs] = v.x;
        sQ[(d4 * 4 + 1) * 64 + rs] = v.y;
        sQ[(d4 * 4 + 2) * 64 + rs] = v.z;
        sQ[(d4 * 4 + 3) * 64 + rs] = v.w;
    }

    float m_i[4], l_i[4];
    unsigned long long acc[4][4] = {};
#pragma unroll
    for (int i = 0; i < 4; i++) { m_i[i] = -1e30f; l_i[i] = 0.0f; }

    __syncthreads();

    for (int t = 0; t < LL / BKV; t++) {
        const int p0 = t * BKV;

#pragma unroll
        for (int it = 0; it < 8; it++) {
            int idx = tid + it * 256;
            int r = idx >> 5;
            int d4 = idx & 31;
            int p = p0 + r;
            const float* src = (p < PP)
                ? (cK + ((size_t)h * PP + p) * DD + d4 * 4)
                : (g_K + (size_t)(p - PP) * NN + h * DD + d4 * 4);
            float4 v = *(const float4*)src;
            int rs = r ^ ((d4 & 15) << 2);
            sKV[(d4 * 4 + 0) * 64 + rs] = v.x;
            sKV[(d4 * 4 + 1) * 64 + rs] = v.y;
            sKV[(d4 * 4 + 2) * 64 + rs] = v.z;
            sKV[(d4 * 4 + 3) * 64 + rs] = v.w;
        }
        __syncthreads();

        unsigned long long s2[4][2] = {};
#pragma unroll 8
        for (int kk = 0; kk < DD; kk++) {
            int sw = ((kk >> 2) & 15) << 2;
            float4 qv = *(const float4*)&sQ[kk * 64 + ((ty * 4) ^ sw)];
            float4 kv = *(const float4*)&sKV[kk * 64 + ((tx * 4) ^ sw)];
            unsigned long long k01 = pk2(kv.x, kv.y);
            unsigned long long k23 = pk2(kv.z, kv.w);
            unsigned long long qp;
            qp = pk2(qv.x, qv.x); fma2(s2[0][0], qp, k01); fma2(s2[0][1], qp, k23);
            qp = pk2(qv.y, qv.y); fma2(s2[1][0], qp, k01); fma2(s2[1][1], qp, k23);
            qp = pk2(qv.z, qv.z); fma2(s2[2][0], qp, k01); fma2(s2[2][1], qp, k23);
            qp = pk2(qv.w, qv.w); fma2(s2[3][0], qp, k01); fma2(s2[3][1], qp, k23);
        }

#pragma unroll
        for (int i = 0; i < 4; i++) {
            float2 a0 = upk(s2[i][0]), a1 = upk(s2[i][1]);
            float mx = fmaxf(fmaxf(a0.x, a0.y), fmaxf(a1.x, a1.y));
            mx = fmaxf(mx, __shfl_xor_sync(0xffffffffu, mx, 1));
            mx = fmaxf(mx, __shfl_xor_sync(0xffffffffu, mx, 2));
            mx = fmaxf(mx, __shfl_xor_sync(0xffffffffu, mx, 4));
            mx = fmaxf(mx, __shfl_xor_sync(0xffffffffu, mx, 8));
            float mnew = fmaxf(m_i[i], mx);
            float scale = __expf(m_i[i] - mnew);
            m_i[i] = mnew;
            float e0 = __expf(a0.x - mnew);
            float e1 = __expf(a0.y - mnew);
            float e2 = __expf(a1.x - mnew);
            float e3 = __expf(a1.y - mnew);
            float ls = e0 + e1 + e2 + e3;
            ls += __shfl_xor_sync(0xffffffffu, ls, 1);
            ls += __shfl_xor_sync(0xffffffffu, ls, 2);
            ls += __shfl_xor_sync(0xffffffffu, ls, 4);
            ls += __shfl_xor_sync(0xffffffffu, ls, 8);
            l_i[i] = l_i[i] * scale + ls;
            unsigned long long sc = pk2(scale, scale);
            mul2(acc[i][0], sc); mul2(acc[i][1], sc);
            mul2(acc[i][2], sc); mul2(acc[i][3], sc);
            *(float4*)&sP[(ty * 4 + i) * 64 + tx * 4] = make_float4(e0, e1, e2, e3);
        }
        __syncthreads();

#pragma unroll
        for (int it = 0; it < 8; it++) {
            int idx = tid + it * 256;
            int r = idx >> 5;
            int d4 = idx & 31;
            int p = p0 + r;
            const float* src = (p < PP)
                ? (cV + ((size_t)h * PP + p) * DD + d4 * 4)
                : (g_V + (size_t)(p - PP) * NN + h * DD + d4 * 4);
            *(float4*)&sKV[r * DD + d4 * 4] = *(const float4*)src;
        }
        __syncthreads();

#pragma unroll 4
        for (int j = 0; j < BKV; j++) {
            float4 v0 = *(const float4*)&sKV[j * DD + tx * 4];
            float4 v1 = *(const float4*)&sKV[j * DD + 64 + tx * 4];
            unsigned long long vp0 = pk2(v0.x, v0.y);
            unsigned long long vp1 = pk2(v0.z, v0.w);
            unsigned long long vp2 = pk2(v1.x, v1.y);
            unsigned long long vp3 = pk2(v1.z, v1.w);
#pragma unroll
            for (int i = 0; i < 4; i++) {
                float p = sP[(ty * 4 + i) * 64 + j];
                unsigned long long pp = pk2(p, p);
                fma2(acc[i][0], pp, vp0);
                fma2(acc[i][1], pp, vp1);
                fma2(acc[i][2], pp, vp2);
                fma2(acc[i][3], pp, vp3);
            }
        }
        __syncthreads();
    }

#pragma unroll
    for (int i = 0; i < 4; i++) {
        float inv = 1.0f / l_i[i];
        float2 c0 = upk(acc[i][0]), c1 = upk(acc[i][1]);
        float2 c2 = upk(acc[i][2]), c3 = upk(acc[i][3]);
        size_t base = (size_t)(q0 + ty * 4 + i) * NN + h * DD;
        *(float4*)&out[base + tx * 4] =
            make_float4(c0.x * inv, c0.y * inv, c1.x * inv, c1.y * inv);
        *(float4*)&out[base + 64 + tx * 4] =
            make_float4(c2.x * inv, c2.y * inv, c3.x * inv, c3.y * inv);
    }
}

// ================= launch =================
extern "C" void kernel_launch(void* const* d_in, const int* in_sizes, int n_in,
                              void* d_out, int out_size) {
    const float* X  = (const float*)d_in[0];
    const float* Wq = (const float*)d_in[1];
    const float* Wk = (const float*)d_in[2];
    const float* Wv = (const float*)d_in[3];
    const float* cK = (const float*)d_in[4];
    const float* cV = (const float*)d_in[5];
    float* out = (float*)d_out;

    // split-bf16 operand prep
    convert_x_kernel<<<(MM * KK) / (4 * 256), 256>>>(X);
    dim3 gw(NN / 32, KK / 32, 3);
    convert_w_kernel<<<gw, dim3(32, 8)>>>(Wq, Wk, Wv);

    // mma.sync GEMM: Q/K/V projections
    cudaFuncSetAttribute(qkv_gemm_mma, cudaFuncAttributeMaxDynamicSharedMemorySize, GEMM_SMEM);
    dim3 gg(NN / GBN, MM / GBM, 3);
    qkv_gemm_mma<<<gg, 256, GEMM_SMEM>>>();

    // attention (fp32)
    const int smem_bytes = (128 * 64 + 64 * 128 + 64 * 64) * (int)sizeof(float);  // 80 KB
    cudaFuncSetAttribute(attn_kernel, cudaFuncAttributeMaxDynamicSharedMemorySize, smem_bytes);
    dim3 g2(MM / BQ, HH);
    attn_kernel<<<g2, 256, smem_bytes>>>(cK, cV, out);
}

// round 5
// speedup vs baseline: 2.9084x; 2.2130x over previous
#include <cuda_runtime.h>
#include <cuda_bf16.h>
#include <cstdint>

// Problem constants
#define MM 1024
#define NN 4096
#define KK 4096
#define HH 32
#define DD 128
#define PP 4096
#define LL (PP + MM)   // 5120

// ---------------- scratch (__device__ globals per alloc rules) ----------------
// split-bf16 GEMM operands
__device__ __nv_bfloat16 g_Xhi[MM * KK];
__device__ __nv_bfloat16 g_Xlo[MM * KK];
__device__ __nv_bfloat16 g_Wthi[3ull * NN * KK];   // W transposed: [z][n][k]
__device__ __nv_bfloat16 g_Wtlo[3ull * NN * KK];
// attention operands (split bf16)
__device__ __nv_bfloat16 g_Qhi[MM * NN];           // [m][h*128+d]
__device__ __nv_bfloat16 g_Qlo[MM * NN];
__device__ __nv_bfloat16 g_Khi[(size_t)HH * LL * DD];  // [h][p][d]
__device__ __nv_bfloat16 g_Klo[(size_t)HH * LL * DD];
__device__ __nv_bfloat16 g_Vhi[(size_t)HH * LL * DD];
__device__ __nv_bfloat16 g_Vlo[(size_t)HH * LL * DD];

// ================= helpers =================
__device__ __forceinline__ uint32_t smem_to_u32(const void* p) {
    uint32_t a;
    asm("{ .reg .u64 t; cvta.to.shared.u64 t, %1; cvt.u32.u64 %0, t; }" : "=r"(a) : "l"(p));
    return a;
}
__device__ __forceinline__ void cp_async16(uint32_t saddr, const void* gaddr) {
    asm volatile("cp.async.cg.shared.global [%0], [%1], 16;" :: "r"(saddr), "l"(gaddr) : "memory");
}
#define CP_COMMIT() asm volatile("cp.async.commit_group;" ::: "memory")
#define CP_WAIT(n)  asm volatile("cp.async.wait_group %0;" :: "n"(n) : "memory")

__device__ __forceinline__ void ldsm_x4(uint32_t* r, uint32_t addr) {
    asm volatile("ldmatrix.sync.aligned.m8n8.x4.shared.b16 {%0,%1,%2,%3}, [%4];"
                 : "=r"(r[0]), "=r"(r[1]), "=r"(r[2]), "=r"(r[3]) : "r"(addr));
}
__device__ __forceinline__ void ldsm_x4t(uint32_t* r, uint32_t addr) {
    asm volatile("ldmatrix.sync.aligned.m8n8.x4.trans.shared.b16 {%0,%1,%2,%3}, [%4];"
                 : "=r"(r[0]), "=r"(r[1]), "=r"(r[2]), "=r"(r[3]) : "r"(addr));
}
__device__ __forceinline__ void ldsm_x2(uint32_t* r, uint32_t addr) {
    asm volatile("ldmatrix.sync.aligned.m8n8.x2.shared.b16 {%0,%1}, [%2];"
                 : "=r"(r[0]), "=r"(r[1]) : "r"(addr));
}
__device__ __forceinline__ void mma16816(float* d, const uint32_t* a, const uint32_t* b) {
    asm volatile(
        "mma.sync.aligned.m16n8k16.row.col.f32.bf16.bf16.f32 "
        "{%0,%1,%2,%3}, {%4,%5,%6,%7}, {%8,%9}, {%0,%1,%2,%3};"
        : "+f"(d[0]), "+f"(d[1]), "+f"(d[2]), "+f"(d[3])
        : "r"(a[0]), "r"(a[1]), "r"(a[2]), "r"(a[3]), "r"(b[0]), "r"(b[1]));
}
__device__ __forceinline__ uint32_t pkbf(float x, float y) {
    __nv_bfloat162 t;
    t.x = __float2bfloat16(x);
    t.y = __float2bfloat16(y);
    return *reinterpret_cast<uint32_t*>(&t);
}

// ================= conversion kernels =================
__global__ __launch_bounds__(256)
void convert_x_kernel(const float* __restrict__ X) {
    int i = (blockIdx.x * 256 + threadIdx.x) * 4;
    float4 v = *(const float4*)(X + i);
    float f[4] = {v.x, v.y, v.z, v.w};
    __align__(8) __nv_bfloat16 hi[4];
    __align__(8) __nv_bfloat16 lo[4];
#pragma unroll
    for (int j = 0; j < 4; j++) {
        hi[j] = __float2bfloat16(f[j]);
        lo[j] = __float2bfloat16(f[j] - __bfloat162float(hi[j]));
    }
    *(uint2*)&g_Xhi[i] = *(uint2*)hi;
    *(uint2*)&g_Xlo[i] = *(uint2*)lo;
}

// W [K][N] -> Wt hi/lo [N][K]
__global__ __launch_bounds__(256)
void convert_w_kernel(const float* __restrict__ Wq, const float* __restrict__ Wk,
                      const float* __restrict__ Wv) {
    const int z = blockIdx.z;
    const float* W = (z == 0) ? Wq : (z == 1) ? Wk : Wv;
    __shared__ float t[32][33];
    const int n0 = blockIdx.x * 32;
    const int k0 = blockIdx.y * 32;
    const int tx = threadIdx.x;
    const int ty = threadIdx.y;
#pragma unroll
    for (int i = 0; i < 4; i++)
        t[ty + i * 8][tx] = W[(size_t)(k0 + ty + i * 8) * NN + n0 + tx];
    __syncthreads();
    size_t base = (size_t)z * NN * KK;
#pragma unroll
    for (int i = 0; i < 4; i++) {
        int r = ty + i * 8;
        float v = t[tx][r];
        __nv_bfloat16 h = __float2bfloat16(v);
        __nv_bfloat16 l = __float2bfloat16(v - __bfloat162float(h));
        size_t o = base + (size_t)(n0 + r) * KK + k0 + tx;
        g_Wthi[o] = h;
        g_Wtlo[o] = l;
    }
}

// caches: cK/cV [H][P][D] fp32 -> g_K*/g_V* [H][L][D] bf16 hi/lo (rows 0..P-1)
__global__ __launch_bounds__(256)
void convert_cache_kernel(const float* __restrict__ cK, const float* __restrict__ cV) {
    const float* src = (blockIdx.y == 0) ? cK : cV;
    __nv_bfloat16* dhi = (blockIdx.y == 0) ? g_Khi : g_Vhi;
    __nv_bfloat16* dlo = (blockIdx.y == 0) ? g_Klo : g_Vlo;
    size_t i = ((size_t)blockIdx.x * 256 + threadIdx.x) * 4;
    float4 v = *(const float4*)(src + i);
    float f[4] = {v.x, v.y, v.z, v.w};
    __align__(8) __nv_bfloat16 hi[4];
    __align__(8) __nv_bfloat16 lo[4];
#pragma unroll
    for (int j = 0; j < 4; j++) {
        hi[j] = __float2bfloat16(f[j]);
        lo[j] = __float2bfloat16(f[j] - __bfloat162float(hi[j]));
    }
    size_t h = i >> 19;                       // / (P*D = 524288)
    size_t inner = i & ((size_t)(PP * DD) - 1);
    size_t o = h * ((size_t)LL * DD) + inner;
    *(uint2*)&dhi[o] = *(uint2*)hi;
    *(uint2*)&dlo[o] = *(uint2*)lo;
}

// ================= split-bf16 mma.sync GEMM: proj = X @ W =================
// grid = (NN/128, MM/128, 3); block = 256 (2x4 warps). Epilogue emits bf16 hi/lo.
#define GBM 128
#define GBN 128
#define GBK 32
#define NCHUNK (KK / GBK)

#define ST_AHI 0
#define ST_ALO 8192
#define ST_BHI 16384
#define ST_BLO 24576
#define STAGE_SZ 32768
#define GEMM_SMEM (2 * STAGE_SZ)

__device__ __forceinline__ uint32_t sw_off32(int row, int seg) {   // [rows][32 bf16] 64B rows
    return (uint32_t)(row * 64 + ((seg ^ (row & 3)) << 4));
}

__global__ __launch_bounds__(256)
void qkv_gemm_mma() {
    extern __shared__ char smem[];
    const uint32_t sb = smem_to_u32(smem);
    const int tid = threadIdx.x;
    const int wid = tid >> 5;
    const int lane = tid & 31;
    const int wm = wid >> 2;
    const int wn = wid & 3;
    const int z = blockIdx.z;
    const int row0 = blockIdx.y * GBM;
    const int col0 = blockIdx.x * GBN;
    const int head = blockIdx.x;    // GBN == head width

    const __nv_bfloat16* Ahi = g_Xhi + (size_t)row0 * KK;
    const __nv_bfloat16* Alo = g_Xlo + (size_t)row0 * KK;
    const __nv_bfloat16* Bhi = g_Wthi + (size_t)z * NN * KK + (size_t)col0 * KK;
    const __nv_bfloat16* Blo = g_Wtlo + (size_t)z * NN * KK + (size_t)col0 * KK;

    const int lr0 = tid >> 2, ls0 = (tid & 3);
    const int lr1 = (tid + 256) >> 2, ls1 = ls0;

    auto load_stage = [&](int s, int k0) {
        uint32_t stb = sb + s * STAGE_SZ;
        const size_t go0 = (size_t)lr0 * KK + k0 + ls0 * 8;
        const size_t go1 = (size_t)lr1 * KK + k0 + ls1 * 8;
        uint32_t so0 = sw_off32(lr0, ls0), so1 = sw_off32(lr1, ls1);
        cp_async16(stb + ST_AHI + so0, Ahi + go0);
        cp_async16(stb + ST_AHI + so1, Ahi + go1);
        cp_async16(stb + ST_ALO + so0, Alo + go0);
        cp_async16(stb + ST_ALO + so1, Alo + go1);
        cp_async16(stb + ST_BHI + so0, Bhi + go0);
        cp_async16(stb + ST_BHI + so1, Bhi + go1);
        cp_async16(stb + ST_BLO + so0, Blo + go0);
        cp_async16(stb + ST_BLO + so1, Blo + go1);
    };

    float acc[4][4][4] = {};

    load_stage(0, 0);
    CP_COMMIT();

    for (int c = 0; c < NCHUNK; ++c) {
        const int s = c & 1;
        if (c + 1 < NCHUNK) {
            load_stage((c + 1) & 1, (c + 1) * GBK);
            CP_COMMIT();
            CP_WAIT(1);
        } else {
            CP_WAIT(0);
        }
        __syncthreads();

        const uint32_t stb = sb + s * STAGE_SZ;
        const int a_row = (lane & 15);
        const int a_seg = (lane >> 4);
        const int b_row = (lane & 7);
        const int b_seg = ((lane >> 3) & 1);

#pragma unroll
        for (int ks = 0; ks < 2; ++ks) {
            const int segb = ks * 2;
            uint32_t ahi[4][4], alo[4][4], bhi[4][2], blo[4][2];
#pragma unroll
            for (int mf = 0; mf < 4; ++mf) {
                uint32_t off = sw_off32(wm * 64 + mf * 16 + a_row, segb + a_seg);
                ldsm_x4(ahi[mf], stb + ST_AHI + off);
                ldsm_x4(alo[mf], stb + ST_ALO + off);
            }
#pragma unroll
            for (int nf = 0; nf < 4; ++nf) {
                uint32_t off = sw_off32(wn * 32 + nf * 8 + b_row, segb + b_seg);
                ldsm_x2(bhi[nf], stb + ST_BHI + off);
                ldsm_x2(blo[nf], stb + ST_BLO + off);
            }
#pragma unroll
            for (int mf = 0; mf < 4; ++mf)
#pragma unroll
                for (int nf = 0; nf < 4; ++nf) {
                    mma16816(acc[mf][nf], ahi[mf], bhi[nf]);
                    mma16816(acc[mf][nf], ahi[mf], blo[nf]);
                    mma16816(acc[mf][nf], alo[mf], bhi[nf]);
                }
        }
        __syncthreads();
    }

    // epilogue: write split-bf16 directly
    const int erow = lane >> 2;
    const int ecol = (lane & 3) * 2;
#pragma unroll
    for (int mf = 0; mf < 4; ++mf) {
#pragma unroll
        for (int nf = 0; nf < 4; ++nf) {
            int cloc = wn * 32 + nf * 8 + ecol;          // 0..127 within head/tile
#pragma unroll
            for (int rr = 0; rr < 2; ++rr) {
                int rowg = row0 + wm * 64 + mf * 16 + erow + rr * 8;   // global m
                float v0 = acc[mf][nf][rr * 2 + 0];
                float v1 = acc[mf][nf][rr * 2 + 1];
                __nv_bfloat16 h0 = __float2bfloat16(v0);
                __nv_bfloat16 h1 = __float2bfloat16(v1);
                float l0 = v0 - __bfloat162float(h0);
                float l1 = v1 - __bfloat162float(h1);
                uint32_t ph = pkbf(__bfloat162float(h0), __bfloat162float(h1));
                uint32_t pl = pkbf(l0, l1);
                if (z == 0) {
                    size_t o = (size_t)rowg * NN + col0 + cloc;
                    *(uint32_t*)&g_Qhi[o] = ph;
                    *(uint32_t*)&g_Qlo[o] = pl;
                } else {
                    size_t o = ((size_t)head * LL + PP + rowg) * DD + cloc;
                    if (z == 1) { *(uint32_t*)&g_Khi[o] = ph; *(uint32_t*)&g_Klo[o] = pl; }
                    else        { *(uint32_t*)&g_Vhi[o] = ph; *(uint32_t*)&g_Vlo[o] = pl; }
                }
            }
        }
    }
}

// ================= tensor-core flash attention (split bf16, 3-pass) =================
// grid = (MM/64, HH); block = 128 (4 warps, warp = 16 q-rows); smem 96KB, 2 CTAs/SM
#define ABQ 64
#define ATK 64
#define NT_KV (LL / ATK)   // 80

#define AQH 0
#define AQL 16384
#define AKH 32768
#define AKL 49152
#define AVH 65536
#define AVL 81920
#define ATTN_SMEM 98304

// swizzled offset within [rows][128 bf16] tile (256B rows, 16B segs 0..15)
__device__ __forceinline__ uint32_t sw_off128(int row, int seg) {
    return (uint32_t)(row * 256 + ((seg ^ (row & 7)) << 4));
}

__global__ __launch_bounds__(128, 2)
void attn_mma_kernel(float* __restrict__ out) {
    extern __shared__ char smem[];
    const uint32_t sb = smem_to_u32(smem);
    const int tid = threadIdx.x;
    const int lane = tid & 31;
    const int wq = tid >> 5;             // warp 0..3 -> q rows wq*16
    const int h = blockIdx.y;
    const int q0 = blockIdx.x * ABQ;

    const __nv_bfloat16* Kh = g_Khi + (size_t)h * LL * DD;
    const __nv_bfloat16* Kl = g_Klo + (size_t)h * LL * DD;
    const __nv_bfloat16* Vh = g_Vhi + (size_t)h * LL * DD;
    const __nv_bfloat16* Vl = g_Vlo + (size_t)h * LL * DD;

    // ---- issue Q load (group 0) ----
#pragma unroll
    for (int i = 0; i < 8; i++) {
        int idx = tid + i * 128;
        int row = idx >> 4, seg = idx & 15;
        uint32_t so = sw_off128(row, seg);
        size_t go = (size_t)(q0 + row) * NN + h * DD + seg * 8;
        cp_async16(sb + AQH + so, g_Qhi + go);
        cp_async16(sb + AQL + so, g_Qlo + go);
    }
    CP_COMMIT();

    auto load_kv = [&](uint32_t dH, uint32_t dL, const __nv_bfloat16* sH,
                       const __nv_bfloat16* sL, int p0) {
#pragma unroll
        for (int i = 0; i < 8; i++) {
            int idx = tid + i * 128;
            int row = idx >> 4, seg = idx & 15;
            uint32_t so = sw_off128(row, seg);
            size_t go = (size_t)(p0 + row) * DD + seg * 8;
            cp_async16(dH + so, sH + go);
            cp_async16(dL + so, sL + go);
        }
        CP_COMMIT();
    };

    load_kv(sb + AKH, sb + AKL, Kh, Kl, 0);   // K0
    load_kv(sb + AVH, sb + AVL, Vh, Vl, 0);   // V0

    float oacc[16][4] = {};                    // 16 d-tiles x (rows g,g+8 x 2 cols)
    float m_s[2] = {-1e30f, -1e30f};
    float l_s[2] = {0.0f, 0.0f};

    // ldmatrix lane address components
    const int a_row = wq * 16 + (lane & 15);                    // Q A-frag row
    const int b_row = ((lane >> 4) & 1) * 8 + (lane & 7);       // K B-frag row base add j*16
    const int bsegl = (lane >> 3) & 1;                          // K B seg low bit
    const int v_row = ((lane >> 3) & 1) * 8 + (lane & 7);       // V trans row base add ks*16
    const int v_seg = lane >> 4;                                // V seg add dt2*2

    for (int t = 0; t < NT_KV; ++t) {
        CP_WAIT(1);                 // K(t) (and Q) ready; V(t) in flight
        __syncthreads();

        // ---- S = Q K^T tile (16 x 64 per warp), 3-pass split ----
        float sacc[8][4] = {};
#pragma unroll
        for (int ksd = 0; ksd < 8; ++ksd) {
            uint32_t ah[4], al[4];
            uint32_t aoff = sw_off128(a_row, ksd * 2 + (lane >> 4));
            ldsm_x4(ah, sb + AQH + aoff);
            ldsm_x4(al, sb + AQL + aoff);
#pragma unroll
            for (int j = 0; j < 4; ++j) {
                uint32_t bh[4], bl[4];
                uint32_t boff = sw_off128(j * 16 + b_row, ksd * 2 + bsegl);
                ldsm_x4(bh, sb + AKH + boff);
                ldsm_x4(bl, sb + AKL + boff);
                mma16816(sacc[2 * j], ah, bh);
                mma16816(sacc[2 * j], ah, bh + 0 == 0 ? bl : bl);  // (kept explicit below)
                // note: compiler folds; real sequence:
                mma16816(sacc[2 * j], al, bh);
                mma16816(sacc[2 * j + 1], ah, bh + 2);
                mma16816(sacc[2 * j + 1], ah, bl + 2);
                mma16816(sacc[2 * j + 1], al, bh + 2);
            }
        }

        // ---- online softmax (rows g and g+8) ----
        uint32_t pa_hi[16], pa_lo[16];
#pragma unroll
        for (int rh = 0; rh < 2; ++rh) {
            float mx = -1e30f;
#pragma unroll
            for (int nt = 0; nt < 8; ++nt)
                mx = fmaxf(mx, fmaxf(sacc[nt][rh * 2], sacc[nt][rh * 2 + 1]));
            mx = fmaxf(mx, __shfl_xor_sync(0xffffffffu, mx, 1));
            mx = fmaxf(mx, __shfl_xor_sync(0xffffffffu, mx, 2));
            float mnew = fmaxf(m_s[rh], mx);
            float sc = __expf(m_s[rh] - mnew);
            m_s[rh] = mnew;
            float sum = 0.0f;
#pragma unroll
            for (int nt = 0; nt < 8; ++nt) {
                float e0 = __expf(sacc[nt][rh * 2] - mnew);
                float e1 = __expf(sacc[nt][rh * 2 + 1] - mnew);
                sacc[nt][rh * 2] = e0;
                sacc[nt][rh * 2 + 1] = e1;
                sum += e0 + e1;
            }
            sum += __shfl_xor_sync(0xffffffffu, sum, 1);
            sum += __shfl_xor_sync(0xffffffffu, sum, 2);
            l_s[rh] = l_s[rh] * sc + sum;
#pragma unroll
            for (int dt = 0; dt < 16; ++dt) {
                oacc[dt][rh * 2] *= sc;
                oacc[dt][rh * 2 + 1] *= sc;
            }
        }
        // P -> split-bf16 A fragments (in-register, C-layout == A-layout identity)
#pragma unroll
        for (int ks = 0; ks < 4; ++ks) {
#pragma unroll
            for (int half = 0; half < 2; ++half) {
                int nt = 2 * ks + half;
#pragma unroll
                for (int rh = 0; rh < 2; ++rh) {
                    float v0 = sacc[nt][rh * 2], v1 = sacc[nt][rh * 2 + 1];
                    __nv_bfloat16 h0 = __float2bfloat16(v0);
                    __nv_bfloat16 h1 = __float2bfloat16(v1);
                    pa_hi[ks * 4 + half * 2 + rh] = pkbf(__bfloat162float(h0), __bfloat162float(h1));
                    pa_lo[ks * 4 + half * 2 + rh] =
                        pkbf(v0 - __bfloat162float(h0), v1 - __bfloat162float(h1));
                }
            }
        }

        CP_WAIT(0);                 // V(t) ready; all warps past K reads
        __syncthreads();
        if (t + 1 < NT_KV) load_kv(sb + AKH, sb + AKL, Kh, Kl, (t + 1) * ATK);

        // ---- O += P V (3-pass split), V via ldmatrix.trans ----
#pragma unroll
        for (int ks = 0; ks < 4; ++ks) {
            const uint32_t* ph = pa_hi + ks * 4;
            const uint32_t* pl = pa_lo + ks * 4;
#pragma unroll
            for (int dt2 = 0; dt2 < 8; ++dt2) {
                uint32_t vh[4], vl[4];
                uint32_t voff = sw_off128(ks * 16 + v_row, dt2 * 2 + v_seg);
                ldsm_x4t(vh, sb + AVH + voff);
                ldsm_x4t(vl, sb + AVL + voff);
                mma16816(oacc[2 * dt2], ph, vh);
                mma16816(oacc[2 * dt2], ph, vl);
                mma16816(oacc[2 * dt2], pl, vh);
                mma16816(oacc[2 * dt2 + 1], ph, vh + 2);
                mma16816(oacc[2 * dt2 + 1], ph, vl + 2);
                mma16816(oacc[2 * dt2 + 1], pl, vh + 2);
            }
        }
        __syncthreads();
        if (t + 1 < NT_KV) load_kv(sb + AVH, sb + AVL, Vh, Vl, (t + 1) * ATK);
    }

    // ---- epilogue ----
    const int g = lane >> 2;
    const int tg = lane & 3;
    float inv0 = 1.0f / l_s[0];
    float inv1 = 1.0f / l_s[1];
    int row0 = q0 + wq * 16 + g;
#pragma unroll
    for (int dt = 0; dt < 16; ++dt) {
        int col = h * DD + dt * 8 + tg * 2;
        *(float2*)&out[(size_t)row0 * NN + col] =
            make_float2(oacc[dt][0] * inv0, oacc[dt][1] * inv0);
        *(float2*)&out[(size_t)(row0 + 8) * NN + col] =
            make_float2(oacc[dt][2] * inv1, oacc[dt][3] * inv1);
    }
}

// ================= launch =================
extern "C" void kernel_launch(void* const* d_in, const int* in_sizes, int n_in,
                              void* d_out, int out_size) {
    const float* X  = (const float*)d_in[0];
    const float* Wq = (const float*)d_in[1];
    const float* Wk = (const float*)d_in[2];
    const float* Wv = (const float*)d_in[3];
    const float* cK = (const float*)d_in[4];
    const float* cV = (const float*)d_in[5];
    float* out = (float*)d_out;

    convert_x_kernel<<<(MM * KK) / (4 * 256), 256>>>(X);
    dim3 gw(NN / 32, KK / 32, 3);
    convert_w_kernel<<<gw, dim3(32, 8)>>>(Wq, Wk, Wv);
    dim3 gc((unsigned)(((size_t)HH * PP * DD) / (4 * 256)), 2);
    convert_cache_kernel<<<gc, 256>>>(cK, cV);

    cudaFuncSetAttribute(qkv_gemm_mma, cudaFuncAttributeMaxDynamicSharedMemorySize, GEMM_SMEM);
    dim3 gg(NN / GBN, MM / GBM, 3);
    qkv_gemm_mma<<<gg, 256, GEMM_SMEM>>>();

    cudaFuncSetAttribute(attn_mma_kernel, cudaFuncAttributeMaxDynamicSharedMemorySize, ATTN_SMEM);
    dim3 ga(MM / ABQ, HH);
    attn_mma_kernel<<<ga, 128, ATTN_SMEM>>>(out);
}

// round 6
// speedup vs baseline: 2.9108x; 1.0008x over previous
#include <cuda_runtime.h>
#include <cuda_bf16.h>
#include <cstdint>

// Problem constants
#define MM 1024
#define NN 4096
#define KK 4096
#define HH 32
#define DD 128
#define PP 4096
#define LL (PP + MM)   // 5120

// ---------------- scratch (__device__ globals per alloc rules) ----------------
// split-bf16 GEMM operands
__device__ __nv_bfloat16 g_Xhi[MM * KK];
__device__ __nv_bfloat16 g_Xlo[MM * KK];
__device__ __nv_bfloat16 g_Wthi[3ull * NN * KK];   // W transposed: [z][n][k]
__device__ __nv_bfloat16 g_Wtlo[3ull * NN * KK];
// attention operands (split bf16)
__device__ __nv_bfloat16 g_Qhi[MM * NN];           // [m][h*128+d]
__device__ __nv_bfloat16 g_Qlo[MM * NN];
__device__ __nv_bfloat16 g_Khi[(size_t)HH * LL * DD];  // [h][p][d]
__device__ __nv_bfloat16 g_Klo[(size_t)HH * LL * DD];
__device__ __nv_bfloat16 g_Vhi[(size_t)HH * LL * DD];
__device__ __nv_bfloat16 g_Vlo[(size_t)HH * LL * DD];

// ================= helpers =================
__device__ __forceinline__ uint32_t smem_to_u32(const void* p) {
    uint32_t a;
    asm("{ .reg .u64 t; cvta.to.shared.u64 t, %1; cvt.u32.u64 %0, t; }" : "=r"(a) : "l"(p));
    return a;
}
__device__ __forceinline__ void cp_async16(uint32_t saddr, const void* gaddr) {
    asm volatile("cp.async.cg.shared.global [%0], [%1], 16;" :: "r"(saddr), "l"(gaddr) : "memory");
}
#define CP_COMMIT() asm volatile("cp.async.commit_group;" ::: "memory")
#define CP_WAIT(n)  asm volatile("cp.async.wait_group %0;" :: "n"(n) : "memory")

__device__ __forceinline__ void ldsm_x4(uint32_t* r, uint32_t addr) {
    asm volatile("ldmatrix.sync.aligned.m8n8.x4.shared.b16 {%0,%1,%2,%3}, [%4];"
                 : "=r"(r[0]), "=r"(r[1]), "=r"(r[2]), "=r"(r[3]) : "r"(addr));
}
__device__ __forceinline__ void ldsm_x4t(uint32_t* r, uint32_t addr) {
    asm volatile("ldmatrix.sync.aligned.m8n8.x4.trans.shared.b16 {%0,%1,%2,%3}, [%4];"
                 : "=r"(r[0]), "=r"(r[1]), "=r"(r[2]), "=r"(r[3]) : "r"(addr));
}
__device__ __forceinline__ void ldsm_x2(uint32_t* r, uint32_t addr) {
    asm volatile("ldmatrix.sync.aligned.m8n8.x2.shared.b16 {%0,%1}, [%2];"
                 : "=r"(r[0]), "=r"(r[1]) : "r"(addr));
}
__device__ __forceinline__ void mma16816(float* d, const uint32_t* a, const uint32_t* b) {
    asm volatile(
        "mma.sync.aligned.m16n8k16.row.col.f32.bf16.bf16.f32 "
        "{%0,%1,%2,%3}, {%4,%5,%6,%7}, {%8,%9}, {%0,%1,%2,%3};"
        : "+f"(d[0]), "+f"(d[1]), "+f"(d[2]), "+f"(d[3])
        : "r"(a[0]), "r"(a[1]), "r"(a[2]), "r"(a[3]), "r"(b[0]), "r"(b[1]));
}
__device__ __forceinline__ uint32_t pkbf(float x, float y) {
    __nv_bfloat162 t;
    t.x = __float2bfloat16(x);
    t.y = __float2bfloat16(y);
    return *reinterpret_cast<uint32_t*>(&t);
}

// ================= conversion kernels =================
__global__ __launch_bounds__(256)
void convert_x_kernel(const float* __restrict__ X) {
    int i = (blockIdx.x * 256 + threadIdx.x) * 4;
    float4 v = *(const float4*)(X + i);
    float f[4] = {v.x, v.y, v.z, v.w};
    __align__(8) __nv_bfloat16 hi[4];
    __align__(8) __nv_bfloat16 lo[4];
#pragma unroll
    for (int j = 0; j < 4; j++) {
        hi[j] = __float2bfloat16(f[j]);
        lo[j] = __float2bfloat16(f[j] - __bfloat162float(hi[j]));
    }
    *(uint2*)&g_Xhi[i] = *(uint2*)hi;
    *(uint2*)&g_Xlo[i] = *(uint2*)lo;
}

// W [K][N] -> Wt hi/lo [N][K]
__global__ __launch_bounds__(256)
void convert_w_kernel(const float* __restrict__ Wq, const float* __restrict__ Wk,
                      const float* __restrict__ Wv) {
    const int z = blockIdx.z;
    const float* W = (z == 0) ? Wq : (z == 1) ? Wk : Wv;
    __shared__ float t[32][33];
    const int n0 = blockIdx.x * 32;
    const int k0 = blockIdx.y * 32;
    const int tx = threadIdx.x;
    const int ty = threadIdx.y;
#pragma unroll
    for (int i = 0; i < 4; i++)
        t[ty + i * 8][tx] = W[(size_t)(k0 + ty + i * 8) * NN + n0 + tx];
    __syncthreads();
    size_t base = (size_t)z * NN * KK;
#pragma unroll
    for (int i = 0; i < 4; i++) {
        int r = ty + i * 8;
        float v = t[tx][r];
        __nv_bfloat16 h = __float2bfloat16(v);
        __nv_bfloat16 l = __float2bfloat16(v - __bfloat162float(h));
        size_t o = base + (size_t)(n0 + r) * KK + k0 + tx;
        g_Wthi[o] = h;
        g_Wtlo[o] = l;
    }
}

// caches: cK/cV [H][P][D] fp32 -> g_K*/g_V* [H][L][D] bf16 hi/lo (rows 0..P-1)
__global__ __launch_bounds__(256)
void convert_cache_kernel(const float* __restrict__ cK, const float* __restrict__ cV) {
    const float* src = (blockIdx.y == 0) ? cK : cV;
    __nv_bfloat16* dhi = (blockIdx.y == 0) ? g_Khi : g_Vhi;
    __nv_bfloat16* dlo = (blockIdx.y == 0) ? g_Klo : g_Vlo;
    size_t i = ((size_t)blockIdx.x * 256 + threadIdx.x) * 4;
    float4 v = *(const float4*)(src + i);
    float f[4] = {v.x, v.y, v.z, v.w};
    __align__(8) __nv_bfloat16 hi[4];
    __align__(8) __nv_bfloat16 lo[4];
#pragma unroll
    for (int j = 0; j < 4; j++) {
        hi[j] = __float2bfloat16(f[j]);
        lo[j] = __float2bfloat16(f[j] - __bfloat162float(hi[j]));
    }
    size_t h = i >> 19;                       // / (P*D = 524288)
    size_t inner = i & ((size_t)(PP * DD) - 1);
    size_t o = h * ((size_t)LL * DD) + inner;
    *(uint2*)&dhi[o] = *(uint2*)hi;
    *(uint2*)&dlo[o] = *(uint2*)lo;
}

// ================= split-bf16 mma.sync GEMM: proj = X @ W =================
// grid = (NN/128, MM/128, 3); block = 256 (2x4 warps). Epilogue emits bf16 hi/lo.
#define GBM 128
#define GBN 128
#define GBK 32
#define NCHUNK (KK / GBK)

#define ST_AHI 0
#define ST_ALO 8192
#define ST_BHI 16384
#define ST_BLO 24576
#define STAGE_SZ 32768
#define GEMM_SMEM (2 * STAGE_SZ)

__device__ __forceinline__ uint32_t sw_off32(int row, int seg) {   // [rows][32 bf16] 64B rows
    return (uint32_t)(row * 64 + ((seg ^ (row & 3)) << 4));
}

__global__ __launch_bounds__(256)
void qkv_gemm_mma() {
    extern __shared__ char smem[];
    const uint32_t sb = smem_to_u32(smem);
    const int tid = threadIdx.x;
    const int wid = tid >> 5;
    const int lane = tid & 31;
    const int wm = wid >> 2;
    const int wn = wid & 3;
    const int z = blockIdx.z;
    const int row0 = blockIdx.y * GBM;
    const int col0 = blockIdx.x * GBN;
    const int head = blockIdx.x;    // GBN == head width

    const __nv_bfloat16* Ahi = g_Xhi + (size_t)row0 * KK;
    const __nv_bfloat16* Alo = g_Xlo + (size_t)row0 * KK;
    const __nv_bfloat16* Bhi = g_Wthi + (size_t)z * NN * KK + (size_t)col0 * KK;
    const __nv_bfloat16* Blo = g_Wtlo + (size_t)z * NN * KK + (size_t)col0 * KK;

    const int lr0 = tid >> 2, ls0 = (tid & 3);
    const int lr1 = (tid + 256) >> 2, ls1 = ls0;

    auto load_stage = [&](int s, int k0) {
        uint32_t stb = sb + s * STAGE_SZ;
        const size_t go0 = (size_t)lr0 * KK + k0 + ls0 * 8;
        const size_t go1 = (size_t)lr1 * KK + k0 + ls1 * 8;
        uint32_t so0 = sw_off32(lr0, ls0), so1 = sw_off32(lr1, ls1);
        cp_async16(stb + ST_AHI + so0, Ahi + go0);
        cp_async16(stb + ST_AHI + so1, Ahi + go1);
        cp_async16(stb + ST_ALO + so0, Alo + go0);
        cp_async16(stb + ST_ALO + so1, Alo + go1);
        cp_async16(stb + ST_BHI + so0, Bhi + go0);
        cp_async16(stb + ST_BHI + so1, Bhi + go1);
        cp_async16(stb + ST_BLO + so0, Blo + go0);
        cp_async16(stb + ST_BLO + so1, Blo + go1);
    };

    float acc[4][4][4] = {};

    load_stage(0, 0);
    CP_COMMIT();

    for (int c = 0; c < NCHUNK; ++c) {
        const int s = c & 1;
        if (c + 1 < NCHUNK) {
            load_stage((c + 1) & 1, (c + 1) * GBK);
            CP_COMMIT();
            CP_WAIT(1);
        } else {
            CP_WAIT(0);
        }
        __syncthreads();

        const uint32_t stb = sb + s * STAGE_SZ;
        const int a_row = (lane & 15);
        const int a_seg = (lane >> 4);
        const int b_row = (lane & 7);
        const int b_seg = ((lane >> 3) & 1);

#pragma unroll
        for (int ks = 0; ks < 2; ++ks) {
            const int segb = ks * 2;
            uint32_t ahi[4][4], alo[4][4], bhi[4][2], blo[4][2];
#pragma unroll
            for (int mf = 0; mf < 4; ++mf) {
                uint32_t off = sw_off32(wm * 64 + mf * 16 + a_row, segb + a_seg);
                ldsm_x4(ahi[mf], stb + ST_AHI + off);
                ldsm_x4(alo[mf], stb + ST_ALO + off);
            }
#pragma unroll
            for (int nf = 0; nf < 4; ++nf) {
                uint32_t off = sw_off32(wn * 32 + nf * 8 + b_row, segb + b_seg);
                ldsm_x2(bhi[nf], stb + ST_BHI + off);
                ldsm_x2(blo[nf], stb + ST_BLO + off);
            }
#pragma unroll
            for (int mf = 0; mf < 4; ++mf)
#pragma unroll
                for (int nf = 0; nf < 4; ++nf) {
                    mma16816(acc[mf][nf], ahi[mf], bhi[nf]);
                    mma16816(acc[mf][nf], ahi[mf], blo[nf]);
                    mma16816(acc[mf][nf], alo[mf], bhi[nf]);
                }
        }
        __syncthreads();
    }

    // epilogue: write split-bf16 directly
    const int erow = lane >> 2;
    const int ecol = (lane & 3) * 2;
#pragma unroll
    for (int mf = 0; mf < 4; ++mf) {
#pragma unroll
        for (int nf = 0; nf < 4; ++nf) {
            int cloc = wn * 32 + nf * 8 + ecol;          // 0..127 within head/tile
#pragma unroll
            for (int rr = 0; rr < 2; ++rr) {
                int rowg = row0 + wm * 64 + mf * 16 + erow + rr * 8;   // global m
                float v0 = acc[mf][nf][rr * 2 + 0];
                float v1 = acc[mf][nf][rr * 2 + 1];
                __nv_bfloat16 h0 = __float2bfloat16(v0);
                __nv_bfloat16 h1 = __float2bfloat16(v1);
                float l0 = v0 - __bfloat162float(h0);
                float l1 = v1 - __bfloat162float(h1);
                uint32_t ph = pkbf(__bfloat162float(h0), __bfloat162float(h1));
                uint32_t pl = pkbf(l0, l1);
                if (z == 0) {
                    size_t o = (size_t)rowg * NN + col0 + cloc;
                    *(uint32_t*)&g_Qhi[o] = ph;
                    *(uint32_t*)&g_Qlo[o] = pl;
                } else {
                    size_t o = ((size_t)head * LL + PP + rowg) * DD + cloc;
                    if (z == 1) { *(uint32_t*)&g_Khi[o] = ph; *(uint32_t*)&g_Klo[o] = pl; }
                    else        { *(uint32_t*)&g_Vhi[o] = ph; *(uint32_t*)&g_Vlo[o] = pl; }
                }
            }
        }
    }
}

// ================= tensor-core flash attention (split bf16, 3-pass) =================
// grid = (MM/64, HH); block = 128 (4 warps, warp = 16 q-rows); smem 96KB, 2 CTAs/SM
#define ABQ 64
#define ATK 64
#define NT_KV (LL / ATK)   // 80

#define AQH 0
#define AQL 16384
#define AKH 32768
#define AKL 49152
#define AVH 65536
#define AVL 81920
#define ATTN_SMEM 98304

// swizzled offset within [rows][128 bf16] tile (256B rows, 16B segs 0..15)
__device__ __forceinline__ uint32_t sw_off128(int row, int seg) {
    return (uint32_t)(row * 256 + ((seg ^ (row & 7)) << 4));
}

__global__ __launch_bounds__(128, 2)
void attn_mma_kernel(float* __restrict__ out) {
    extern __shared__ char smem[];
    const uint32_t sb = smem_to_u32(smem);
    const int tid = threadIdx.x;
    const int lane = tid & 31;
    const int wq = tid >> 5;             // warp 0..3 -> q rows wq*16
    const int h = blockIdx.y;
    const int q0 = blockIdx.x * ABQ;

    const __nv_bfloat16* Kh = g_Khi + (size_t)h * LL * DD;
    const __nv_bfloat16* Kl = g_Klo + (size_t)h * LL * DD;
    const __nv_bfloat16* Vh = g_Vhi + (size_t)h * LL * DD;
    const __nv_bfloat16* Vl = g_Vlo + (size_t)h * LL * DD;

    // ---- issue Q load (group 0) ----
#pragma unroll
    for (int i = 0; i < 8; i++) {
        int idx = tid + i * 128;
        int row = idx >> 4, seg = idx & 15;
        uint32_t so = sw_off128(row, seg);
        size_t go = (size_t)(q0 + row) * NN + h * DD + seg * 8;
        cp_async16(sb + AQH + so, g_Qhi + go);
        cp_async16(sb + AQL + so, g_Qlo + go);
    }
    CP_COMMIT();

    auto load_kv = [&](uint32_t dH, uint32_t dL, const __nv_bfloat16* sH,
                       const __nv_bfloat16* sL, int p0) {
#pragma unroll
        for (int i = 0; i < 8; i++) {
            int idx = tid + i * 128;
            int row = idx >> 4, seg = idx & 15;
            uint32_t so = sw_off128(row, seg);
            size_t go = (size_t)(p0 + row) * DD + seg * 8;
            cp_async16(dH + so, sH + go);
            cp_async16(dL + so, sL + go);
        }
        CP_COMMIT();
    };

    load_kv(sb + AKH, sb + AKL, Kh, Kl, 0);   // K0
    load_kv(sb + AVH, sb + AVL, Vh, Vl, 0);   // V0

    float oacc[16][4] = {};                    // 16 d-tiles x (rows g,g+8 x 2 cols)
    float m_s[2] = {-1e30f, -1e30f};
    float l_s[2] = {0.0f, 0.0f};

    // ldmatrix lane address components
    const int a_row = wq * 16 + (lane & 15);                    // Q A-frag row
    const int b_row = ((lane >> 4) & 1) * 8 + (lane & 7);       // K B-frag row base add j*16
    const int bsegl = (lane >> 3) & 1;                          // K B seg low bit
    const int v_row = ((lane >> 3) & 1) * 8 + (lane & 7);       // V trans row base add ks*16
    const int v_seg = lane >> 4;                                // V seg add dt2*2

    for (int t = 0; t < NT_KV; ++t) {
        CP_WAIT(1);                 // K(t) (and Q) ready; V(t) in flight
        __syncthreads();

        // ---- S = Q K^T tile (16 x 64 per warp), 3-pass split ----
        float sacc[8][4] = {};
#pragma unroll
        for (int ksd = 0; ksd < 8; ++ksd) {
            uint32_t ah[4], al[4];
            uint32_t aoff = sw_off128(a_row, ksd * 2 + (lane >> 4));
            ldsm_x4(ah, sb + AQH + aoff);
            ldsm_x4(al, sb + AQL + aoff);
#pragma unroll
            for (int j = 0; j < 4; ++j) {
                uint32_t bh[4], bl[4];
                uint32_t boff = sw_off128(j * 16 + b_row, ksd * 2 + bsegl);
                ldsm_x4(bh, sb + AKH + boff);
                ldsm_x4(bl, sb + AKL + boff);
                mma16816(sacc[2 * j], ah, bh);
                mma16816(sacc[2 * j], ah, bh + 0 == 0 ? bl : bl);  // (kept explicit below)
                // note: compiler folds; real sequence:
                mma16816(sacc[2 * j], al, bh);
                mma16816(sacc[2 * j + 1], ah, bh + 2);
                mma16816(sacc[2 * j + 1], ah, bl + 2);
                mma16816(sacc[2 * j + 1], al, bh + 2);
            }
        }

        // ---- online softmax (rows g and g+8) ----
        uint32_t pa_hi[16], pa_lo[16];
#pragma unroll
        for (int rh = 0; rh < 2; ++rh) {
            float mx = -1e30f;
#pragma unroll
            for (int nt = 0; nt < 8; ++nt)
                mx = fmaxf(mx, fmaxf(sacc[nt][rh * 2], sacc[nt][rh * 2 + 1]));
            mx = fmaxf(mx, __shfl_xor_sync(0xffffffffu, mx, 1));
            mx = fmaxf(mx, __shfl_xor_sync(0xffffffffu, mx, 2));
            float mnew = fmaxf(m_s[rh], mx);
            float sc = __expf(m_s[rh] - mnew);
            m_s[rh] = mnew;
            float sum = 0.0f;
#pragma unroll
            for (int nt = 0; nt < 8; ++nt) {
                float e0 = __expf(sacc[nt][rh * 2] - mnew);
                float e1 = __expf(sacc[nt][rh * 2 + 1] - mnew);
                sacc[nt][rh * 2] = e0;
                sacc[nt][rh * 2 + 1] = e1;
                sum += e0 + e1;
            }
            sum += __shfl_xor_sync(0xffffffffu, sum, 1);
            sum += __shfl_xor_sync(0xffffffffu, sum, 2);
            l_s[rh] = l_s[rh] * sc + sum;
#pragma unroll
            for (int dt = 0; dt < 16; ++dt) {
                oacc[dt][rh * 2] *= sc;
                oacc[dt][rh * 2 + 1] *= sc;
            }
        }
        // P -> split-bf16 A fragments (in-register, C-layout == A-layout identity)
#pragma unroll
        for (int ks = 0; ks < 4; ++ks) {
#pragma unroll
            for (int half = 0; half < 2; ++half) {
                int nt = 2 * ks + half;
#pragma unroll
                for (int rh = 0; rh < 2; ++rh) {
                    float v0 = sacc[nt][rh * 2], v1 = sacc[nt][rh * 2 + 1];
                    __nv_bfloat16 h0 = __float2bfloat16(v0);
                    __nv_bfloat16 h1 = __float2bfloat16(v1);
                    pa_hi[ks * 4 + half * 2 + rh] = pkbf(__bfloat162float(h0), __bfloat162float(h1));
                    pa_lo[ks * 4 + half * 2 + rh] =
                        pkbf(v0 - __bfloat162float(h0), v1 - __bfloat162float(h1));
                }
            }
        }

        CP_WAIT(0);                 // V(t) ready; all warps past K reads
        __syncthreads();
        if (t + 1 < NT_KV) load_kv(sb + AKH, sb + AKL, Kh, Kl, (t + 1) * ATK);

        // ---- O += P V (3-pass split), V via ldmatrix.trans ----
#pragma unroll
        for (int ks = 0; ks < 4; ++ks) {
            const uint32_t* ph = pa_hi + ks * 4;
            const uint32_t* pl = pa_lo + ks * 4;
#pragma unroll
            for (int dt2 = 0; dt2 < 8; ++dt2) {
                uint32_t vh[4], vl[4];
                uint32_t voff = sw_off128(ks * 16 + v_row, dt2 * 2 + v_seg);
                ldsm_x4t(vh, sb + AVH + voff);
                ldsm_x4t(vl, sb + AVL + voff);
                mma16816(oacc[2 * dt2], ph, vh);
                mma16816(oacc[2 * dt2], ph, vl);
                mma16816(oacc[2 * dt2], pl, vh);
                mma16816(oacc[2 * dt2 + 1], ph, vh + 2);
                mma16816(oacc[2 * dt2 + 1], ph, vl + 2);
                mma16816(oacc[2 * dt2 + 1], pl, vh + 2);
            }
        }
        __syncthreads();
        if (t + 1 < NT_KV) load_kv(sb + AVH, sb + AVL, Vh, Vl, (t + 1) * ATK);
    }

    // ---- epilogue ----
    const int g = lane >> 2;
    const int tg = lane & 3;
    float inv0 = 1.0f / l_s[0];
    float inv1 = 1.0f / l_s[1];
    int row0 = q0 + wq * 16 + g;
#pragma unroll
    for (int dt = 0; dt < 16; ++dt) {
        int col = h * DD + dt * 8 + tg * 2;
        *(float2*)&out[(size_t)row0 * NN + col] =
            make_float2(oacc[dt][0] * inv0, oacc[dt][1] * inv0);
        *(float2*)&out[(size_t)(row0 + 8) * NN + col] =
            make_float2(oacc[dt][2] * inv1, oacc[dt][3] * inv1);
    }
}

// ================= launch =================
extern "C" void kernel_launch(void* const* d_in, const int* in_sizes, int n_in,
                              void* d_out, int out_size) {
    const float* X  = (const float*)d_in[0];
    const float* Wq = (const float*)d_in[1];
    const float* Wk = (const float*)d_in[2];
    const float* Wv = (const float*)d_in[3];
    const float* cK = (const float*)d_in[4];
    const float* cV = (const float*)d_in[5];
    float* out = (float*)d_out;

    convert_x_kernel<<<(MM * KK) / (4 * 256), 256>>>(X);
    dim3 gw(NN / 32, KK / 32, 3);
    convert_w_kernel<<<gw, dim3(32, 8)>>>(Wq, Wk, Wv);
    dim3 gc((unsigned)(((size_t)HH * PP * DD) / (4 * 256)), 2);
    convert_cache_kernel<<<gc, 256>>>(cK, cV);

    cudaFuncSetAttribute(qkv_gemm_mma, cudaFuncAttributeMaxDynamicSharedMemorySize, GEMM_SMEM);
    dim3 gg(NN / GBN, MM / GBM, 3);
    qkv_gemm_mma<<<gg, 256, GEMM_SMEM>>>();

    cudaFuncSetAttribute(attn_mma_kernel, cudaFuncAttributeMaxDynamicSharedMemorySize, ATTN_SMEM);
    dim3 ga(MM / ABQ, HH);
    attn_mma_kernel<<<ga, 128, ATTN_SMEM>>>(out);
}